// round 9
// baseline (speedup 1.0000x reference)
#include <cuda_runtime.h>

#define BATCH 2048
#define TT    512
#define HID   64
#define NB    7       // rows per CTA (296 CTAs = exactly 2 per SM)
#define NCTA  296
#define NTHR  256
#define GBLK  72      // g_s block stride (bank-conflict-free scatter)
#define GROW  (3*GBLK + HID)   // 280 floats per g_s row

typedef unsigned long long u64;

__device__ __forceinline__ u64 ffma2(u64 a, u64 b, u64 c) {
    u64 d;
    asm("fma.rn.f32x2 %0, %1, %2, %3;" : "=l"(d) : "l"(a), "l"(b), "l"(c));
    return d;
}

__device__ __forceinline__ float sum2(u64 v) {
    float lo, hi;
    asm("mov.b64 {%0, %1}, %2;" : "=f"(lo), "=f"(hi) : "l"(v));
    return lo + hi;
}

__device__ __forceinline__ float tanh_fast(float v) {
    float r;
    asm("tanh.approx.f32 %0, %1;" : "=f"(r) : "f"(v));
    return r;
}

__global__ __launch_bounds__(NTHR, 2)
void lstm_kernel(const float* __restrict__ x,
                 const float* __restrict__ W_ih,
                 const float* __restrict__ W_hh,
                 const float* __restrict__ b_ih,
                 const float* __restrict__ b_hh,
                 const float* __restrict__ W_d,
                 const float* __restrict__ b_d,
                 float* __restrict__ out) {
    __shared__ float x_s[NB][TT];      // 14 KB
    __shared__ float h_s[NB][HID];     // 1.75 KB
    __shared__ float g_s[NB][GROW];    // 7.65 KB (gate blocks at 0,72,144,216)

    const int tid  = threadIdx.x;
    const int lane = tid & 31;
    const int warp = tid >> 5;                 // 0..7
    const int q    = lane >> 3;                // k-quarter 0..3 (also final gate id)
    const int m    = (warp << 3) | (lane & 7); // hidden unit 0..63
    const int fcol = m + 64 * q;               // column this thread finalizes
    // branchless activation: act(v) = s0 + s1*tanh(sc*v); gate q==2 is tanh (g)
    const float s0 = (q == 2) ? 0.0f : 0.5f;
    const float s1 = (q == 2) ? 1.0f : 0.5f;
    const float sc = (q == 2) ? 1.0f : 0.5f;

    const int row0 = blockIdx.x * NB;

    // --- weights: k-quarter of all 4 gate columns of unit m (32 u64 = 64 regs) ---
    u64 wq[4][8];
#pragma unroll
    for (int j = 0; j < 4; j++) {
        const ulonglong2* p =
            reinterpret_cast<const ulonglong2*>(W_hh + (m + 64 * j) * HID + q * 16);
#pragma unroll
        for (int v = 0; v < 4; v++) {
            ulonglong2 u = p[v];
            wq[j][2 * v + 0] = u.x;
            wq[j][2 * v + 1] = u.y;
        }
    }
    const float bias = b_ih[fcol] + b_hh[fcol];
    const float wih  = W_ih[fcol];
    const int khoff  = q * 16;

    // --- stage x slab (coalesced; clamp rows past BATCH) ---
    for (int i = tid; i < NB * TT; i += NTHR) {
        int r = i / TT;
        int t = i % TT;
        int gr = row0 + r;
        if (gr > BATCH - 1) gr = BATCH - 1;
        x_s[r][t] = x[gr * TT + t];
    }
    for (int i = tid; i < NB * HID; i += NTHR)
        ((float*)h_s)[i] = 0.0f;

    // --- phase-2 ownership: NB*HID = 448 cell states ---
    float c0 = 0.0f, c1 = 0.0f;
    const int r0a = tid >> 6,            m0 = tid & 63;
    const bool has1 = (tid < NB * HID - NTHR);   // tid < 192
    const int idx1 = tid + NTHR;
    const int r1a = idx1 >> 6,           m1 = idx1 & 63;

    const bool hi2 = (q >= 2);
    const bool odd = (q & 1);

    __syncthreads();

    for (int t = 0; t < TT; t++) {
        float xv[NB];
#pragma unroll
        for (int r = 0; r < NB; r++) xv[r] = x_s[r][t];

        // ---------- phase 1: per-row quarter partials for all 4 gates ----------
#pragma unroll
        for (int r = 0; r < NB; r++) {
            ulonglong2 hv[4];
#pragma unroll
            for (int v = 0; v < 4; v++)       // 4 back-to-back LDS.128 (16 k-values)
                hv[v] = *reinterpret_cast<const ulonglong2*>(&h_s[r][khoff + v * 4]);

            u64 a0 = 0ull, a1 = 0ull, a2 = 0ull, a3 = 0ull;
#pragma unroll
            for (int v = 0; v < 4; v++) {
                a0 = ffma2(wq[0][2 * v + 0], hv[v].x, a0);
                a0 = ffma2(wq[0][2 * v + 1], hv[v].y, a0);
                a1 = ffma2(wq[1][2 * v + 0], hv[v].x, a1);
                a1 = ffma2(wq[1][2 * v + 1], hv[v].y, a1);
                a2 = ffma2(wq[2][2 * v + 0], hv[v].x, a2);
                a2 = ffma2(wq[2][2 * v + 1], hv[v].y, a2);
                a3 = ffma2(wq[3][2 * v + 0], hv[v].x, a3);
                a3 = ffma2(wq[3][2 * v + 1], hv[v].y, a3);
            }
            float p0 = sum2(a0), p1 = sum2(a1), p2 = sum2(a2), p3 = sum2(a3);

            // ---- reduce-scatter over the 4 k-quarters (convergent, branchless) ----
            // round 1 (xor 16): keep (i,f) if q<2 else (g,o); send the other pair
            float sendA = hi2 ? p0 : p2;
            float sendB = hi2 ? p1 : p3;
            float rA = __shfl_xor_sync(0xffffffffu, sendA, 16);
            float rB = __shfl_xor_sync(0xffffffffu, sendB, 16);
            float sA = (hi2 ? p2 : p0) + rA;
            float sB = (hi2 ? p3 : p1) + rB;
            // round 2 (xor 8): keep one of the pair, send the other
            float send2 = odd ? sA : sB;
            float rc = __shfl_xor_sync(0xffffffffu, send2, 8);
            float totp = (odd ? sB : sA) + rc;    // full sum for gate q of unit m

            float tot = fmaf(xv[r], wih, bias) + totp;
            g_s[r][q * GBLK + m] = fmaf(s1, tanh_fast(sc * tot), s0);
        }
        __syncthreads();

        // ---------- phase 2: cell/hidden update ----------
        {
            float i_ = g_s[r0a][0 * GBLK + m0];
            float f_ = g_s[r0a][1 * GBLK + m0];
            float gg = g_s[r0a][2 * GBLK + m0];
            float o_ = g_s[r0a][3 * GBLK + m0];
            c0 = fmaf(f_, c0, i_ * gg);
            h_s[r0a][m0] = o_ * tanh_fast(c0);
        }
        if (has1) {
            float i_ = g_s[r1a][0 * GBLK + m1];
            float f_ = g_s[r1a][1 * GBLK + m1];
            float gg = g_s[r1a][2 * GBLK + m1];
            float o_ = g_s[r1a][3 * GBLK + m1];
            c1 = fmaf(f_, c1, i_ * gg);
            h_s[r1a][m1] = o_ * tanh_fast(c1);
        }
        __syncthreads();
    }

    // ---------- final projection ----------
    if (tid < NB && row0 + tid < BATCH) {
        float s = b_d[0];
#pragma unroll
        for (int mm = 0; mm < HID; mm++)
            s = fmaf(h_s[tid][mm], W_d[mm], s);
        out[row0 + tid] = s;
    }
}

extern "C" void kernel_launch(void* const* d_in, const int* in_sizes, int n_in,
                              void* d_out, int out_size) {
    const float* x    = (const float*)d_in[0];
    const float* W_ih = (const float*)d_in[1];
    const float* W_hh = (const float*)d_in[2];
    const float* b_ih = (const float*)d_in[3];
    const float* b_hh = (const float*)d_in[4];
    const float* W_d  = (const float*)d_in[5];
    const float* b_d  = (const float*)d_in[6];
    float* out = (float*)d_out;

    lstm_kernel<<<NCTA, NTHR>>>(x, W_ih, W_hh, b_ih, b_hh, W_d, b_d, out);
}